// round 15
// baseline (speedup 1.0000x reference)
#include <cuda_runtime.h>
#include <cuda_fp16.h>
#include <cstdint>

// ---------------- problem shape ----------------
#define BATCH 32
#define CIN   64
#define HIN   128
#define WIN   128
#define COUT  128
#define HO    126
#define WO    126
#define NGRP  8
#define HP    63
#define WP    63
#define EPS   1e-5f

#define RSTRIDE 276                    // raw f32 words per ci: 4 rows * 68 + 4 pad
#define VTS  40                        // tile stride in V (32 + 8, lq*40+lr covers 32 banks)
#define VWORDS (64 * 8 * VTS)          // 20480 words = 80 KB
#define UCW  16384                     // words per 4-xi U chunk (64 KB)
#define SMEM_WORDS (VWORDS + 2 * UCW)  // 53248 words = 212992 B (1 CTA/SM)

// ---------------- scratch (static device globals) ----------------
__device__ float    g_pmax[(size_t)BATCH * COUT * HP * WP];
__device__ float    g_pmin[(size_t)BATCH * COUT * HP * WP];
__device__ uint32_t g_wU[64 * 8 * 32 * 4];   // U fragments; per-xi 4096-word blocks
__device__ float    g_sum[BATCH * NGRP];
__device__ float    g_sumsq[BATCH * NGRP];

// non-volatile: allow ptxas to software-pipeline loads across MMAs
static __device__ __forceinline__ void mma_f16(
    float* c, const uint32_t* a, uint32_t b0, uint32_t b1)
{
    asm("mma.sync.aligned.m16n8k16.row.col.f32.f16.f16.f32 "
        "{%0,%1,%2,%3}, {%4,%5,%6,%7}, {%8,%9}, {%0,%1,%2,%3};"
        : "+f"(c[0]), "+f"(c[1]), "+f"(c[2]), "+f"(c[3])
        : "r"(a[0]), "r"(a[1]), "r"(a[2]), "r"(a[3]), "r"(b0), "r"(b1));
}

static __device__ __forceinline__ void cp_async16(uint32_t dst_smem, const void* src) {
    asm volatile("cp.async.ca.shared.global [%0], [%1], 16;"
                 :: "r"(dst_smem), "l"(src) : "memory");
}
static __device__ __forceinline__ void cp_commit() {
    asm volatile("cp.async.commit_group;" ::: "memory");
}
template <int N>
static __device__ __forceinline__ void cp_wait() {
    asm volatile("cp.async.wait_group %0;" :: "n"(N) : "memory");
}
static __device__ __forceinline__ uint32_t smem_u32(const void* p) {
    uint32_t a;
    asm("{ .reg .u64 t; cvta.to.shared.u64 t, %1; cvt.u32.u64 %0, t; }"
        : "=r"(a) : "l"(p));
    return a;
}

// U = G w G^T element (Xi, Nu) for one (cout, ci)
static __device__ __forceinline__ float wino_u(
    const float* __restrict__ W, int cout, int ci, int Xi, int Nu)
{
    const float* w = W + (cout * CIN + ci) * 9;
    float t0, t1, t2;
    if (Xi == 0)      { t0 = w[0]; t1 = w[1]; t2 = w[2]; }
    else if (Xi == 3) { t0 = w[6]; t1 = w[7]; t2 = w[8]; }
    else {
        float s = (Xi == 1) ? 1.f : -1.f;
        t0 = 0.5f * (w[0] + s * w[3] + w[6]);
        t1 = 0.5f * (w[1] + s * w[4] + w[7]);
        t2 = 0.5f * (w[2] + s * w[5] + w[8]);
    }
    if (Nu == 0) return t0;
    if (Nu == 3) return t2;
    float s = (Nu == 1) ? 1.f : -1.f;
    return 0.5f * (t0 + s * t1 + t2);
}

// ---------------- kernel 0: pack U into m16n8k16 fragment layout -------------
// g_wU[((xi*4+cg)*8 + mt)*32*4 ...]: per-xi contiguous 4096-word block.
__global__ __launch_bounds__(256)
void pack_kernel(const float* __restrict__ W)
{
    int idx = blockIdx.x * 256 + threadIdx.x;      // 65536 total
    if (idx < BATCH * NGRP) { g_sum[idx] = 0.f; g_sumsq[idx] = 0.f; }
    if (idx >= 64 * 8 * 32 * 4) return;
    int j      = idx & 3;
    int lane   = (idx >> 2) & 31;
    int mt     = (idx >> 7) & 7;
    int kchunk = idx >> 10;                        // 0..63
    int xi_nu = kchunk >> 2;
    int cg    = kchunk & 3;
    int Xi = xi_nu >> 2, Nu = xi_nu & 3;
    int lr = lane >> 2, lq = lane & 3;
    int r  = lr + (j & 1) * 8;
    int kb = 2 * lq + ((j >> 1) & 1) * 8;
    int cout = mt * 16 + r;
    int ci   = cg * 16 + kb;
    float u0 = wino_u(W, cout, ci,     Xi, Nu);
    float u1 = wino_u(W, cout, ci + 1, Xi, Nu);
    __half2 h = __floats2half2_rn(u0, u1);         // low = ci even
    g_wU[idx] = *reinterpret_cast<uint32_t*>(&h);
}

// ---------------- kernel 1: Winograd F(2x2,3x3) conv + fused pool ------------
// Grid (126, 32): trow = bx>>1, chunk = bx&1. CTA: 512 thr, 128 couts x 32 tiles.
// 16 warps = 8M x 2N; warp = 16 couts x 16 tiles (nt=0..1). warp_m == GN group.
__global__ __launch_bounds__(512, 1)
void conv_wino_kernel(const float* __restrict__ x,
                      const float* __restrict__ bias)
{
    extern __shared__ uint32_t smw[];
    uint32_t* Vs  = smw;                                      // V tiles (f16x2)
    float*    raw = reinterpret_cast<float*>(smw + VWORDS);   // phase-1 only (in U region)
    uint32_t* Us  = smw + VWORDS;                             // phase-2: 2 x UCW
    const uint32_t raw_base = smem_u32(raw);
    const uint32_t us_base  = smem_u32(Us);

    const int tid  = threadIdx.x;
    const int wid  = tid >> 5;              // 0..15
    const int lane = tid & 31;
    const int warp_m = wid >> 1;            // 0..7 = m-tile = GN group
    const int warp_n = wid & 1;             // 0..1
    const int bx = blockIdx.x;
    const int trow  = bx >> 1;              // pooled row 0..62
    const int chunk = bx & 1;
    const int b  = blockIdx.y;
    const int ho0 = trow * 2;
    const int chb = chunk * 64;

    const int lq = lane & 3;
    const int lr = lane >> 2;

    // ======== phase 1: zero pads, bulk cp.async stage (all 64 ci), transform ==
    // zero pad cols 64..67 for every (ci64, row): 256 float4 slots
    if (tid < 256) {
        int ci64 = tid >> 2, row = tid & 3;
        *reinterpret_cast<float4*>(raw + ci64 * RSTRIDE + row * 68 + 64) =
            make_float4(0.f, 0.f, 0.f, 0.f);
    }
    // stage: 64 ci x 4 rows x 17 quads = 4352 tasks
#pragma unroll
    for (int t = 0; t < 9; t++) {
        int task = tid + 512 * t;
        if (task < 4352) {
            int ci64 = task / 68;
            int rem  = task - ci64 * 68;
            int row  = rem / 17;
            int q    = rem - row * 17;
            int col  = chb + q * 4;
            if (col <= 124)
                cp_async16(raw_base + (uint32_t)(ci64 * RSTRIDE + row * 68 + q * 4) * 4,
                           x + (((size_t)b * CIN + ci64) * HIN + (ho0 + row)) * WIN + col);
        }
    }
    cp_commit();
    cp_wait<0>();
    __syncthreads();

    // transform: 1024 tasks (cg, pair, tile); V = B^T d B for 2 ci each
#pragma unroll
    for (int t = 0; t < 2; t++) {
        int task = tid + 512 * t;
        int cg = task >> 8;
        int p  = (task >> 5) & 7;
        int tt = task & 31;
        float V2[2][16];
#pragma unroll
        for (int s = 0; s < 2; s++) {
            const float* rw = raw + (cg * 16 + 2 * p + s) * RSTRIDE + 2 * tt;
            float d[4][4];
#pragma unroll
            for (int r = 0; r < 4; r++) {
                float2 p0 = *reinterpret_cast<const float2*>(rw + r * 68);
                float2 p1 = *reinterpret_cast<const float2*>(rw + r * 68 + 2);
                d[r][0] = p0.x; d[r][1] = p0.y; d[r][2] = p1.x; d[r][3] = p1.y;
            }
            float tm[4][4];
#pragma unroll
            for (int jj = 0; jj < 4; jj++) {
                tm[0][jj] = d[0][jj] - d[2][jj];
                tm[1][jj] = d[1][jj] + d[2][jj];
                tm[2][jj] = d[2][jj] - d[1][jj];
                tm[3][jj] = d[1][jj] - d[3][jj];
            }
#pragma unroll
            for (int ii = 0; ii < 4; ii++) {
                V2[s][ii * 4 + 0] = tm[ii][0] - tm[ii][2];
                V2[s][ii * 4 + 1] = tm[ii][1] + tm[ii][2];
                V2[s][ii * 4 + 2] = tm[ii][2] - tm[ii][1];
                V2[s][ii * 4 + 3] = tm[ii][1] - tm[ii][3];
            }
        }
#pragma unroll
        for (int xi = 0; xi < 16; xi++) {
            __half2 h = __floats2half2_rn(V2[0][xi], V2[1][xi]);
            Vs[((cg * 16 + xi) * 8 + p) * VTS + tt] = *reinterpret_cast<uint32_t*>(&h);
        }
    }
    __syncthreads();      // raw region dead; U staging may now overwrite it

    // ======== phase 2: 4 chunks of 4 xi; U staged via cp.async ========
    auto stageU4 = [&](int uc) {      // stage xi in [uc*4, uc*4+4) -> buf (uc&1)
        const uint32_t dstb = us_base + (uint32_t)(uc & 1) * (UCW * 4);
        const uint4* src = reinterpret_cast<const uint4*>(g_wU + uc * UCW);
#pragma unroll
        for (int t = 0; t < 8; t++) {
            int o = tid + 512 * t;            // 0..4095 uint4
            cp_async16(dstb + (uint32_t)o * 16, src + o);
        }
        cp_commit();
    };

    float Y[2][2][2][4];      // [nt][r][c][frag]
#pragma unroll
    for (int n = 0; n < 2; n++)
#pragma unroll
        for (int r = 0; r < 2; r++)
#pragma unroll
            for (int c = 0; c < 2; c++)
#pragma unroll
                for (int e = 0; e < 4; e++) Y[n][r][c][e] = 0.f;

    const int bcol = warp_n * 16 + lr;      // B tile column base

    stageU4(0);

    for (int uc = 0; uc < 4; uc++) {
        cp_wait<0>();
        __syncthreads();          // U chunk ready; all warps past previous reads
        if (uc + 1 < 4) stageU4(uc + 1);   // DMA overlaps MMAs below

        const uint4* ub = reinterpret_cast<const uint4*>(Us + (uc & 1) * UCW);

#pragma unroll
        for (int xi4 = 0; xi4 < 4; xi4++) {
            const int xi = uc * 4 + xi4;
            const int Xi = xi >> 2, Nu = xi & 3;
            const uint4* ua = ub + xi4 * 1024;     // 4096 words = 1024 uint4

            float M[2][4];
#pragma unroll
            for (int n = 0; n < 2; n++)
#pragma unroll
                for (int e = 0; e < 4; e++) M[n][e] = 0.f;

#pragma unroll
            for (int cg = 0; cg < 4; cg++) {
                uint4 f = ua[(cg * 8 + warp_m) * 32 + lane];
                uint32_t a[4] = { f.x, f.y, f.z, f.w };
                const uint32_t* vb0 = Vs + ((cg * 16 + xi) * 8 + lq)     * VTS + bcol;
                const uint32_t* vb1 = Vs + ((cg * 16 + xi) * 8 + lq + 4) * VTS + bcol;
#pragma unroll
                for (int nt = 0; nt < 2; nt++) {
                    uint32_t b0 = vb0[nt * 8];
                    uint32_t b1 = vb1[nt * 8];
                    mma_f16(M[nt], a, b0, b1);
                }
            }

            // Y[nt][r][c] += A^T[r][Xi] * A^T[c][Nu] * M[nt]
            const int cy[2] = { (Xi < 3) ? 1 : 0,
                                (Xi == 1) ? 1 : ((Xi >= 2) ? -1 : 0) };
            const int cx[2] = { (Nu < 3) ? 1 : 0,
                                (Nu == 1) ? 1 : ((Nu >= 2) ? -1 : 0) };
#pragma unroll
            for (int r = 0; r < 2; r++)
#pragma unroll
                for (int c = 0; c < 2; c++) {
                    const int coef = cy[r] * cx[c];
                    if (coef == 1) {
#pragma unroll
                        for (int n = 0; n < 2; n++)
#pragma unroll
                            for (int e = 0; e < 4; e++) Y[n][r][c][e] += M[n][e];
                    } else if (coef == -1) {
#pragma unroll
                        for (int n = 0; n < 2; n++)
#pragma unroll
                            for (int e = 0; e < 4; e++) Y[n][r][c][e] -= M[n][e];
                    }
                }
        }
    }

    // ======== epilogue: bias, GN partials, fused 2x2 max/min, store ========
    float sacc = 0.f, qacc = 0.f;

    const int c0 = warp_m * 16 + lr;
    const int c1 = c0 + 8;
    const float bv0 = bias[c0];
    const float bv1 = bias[c1];
    float* pmax0 = g_pmax + (((size_t)b * COUT + c0) * HP + trow) * WP;
    float* pmin0 = g_pmin + (((size_t)b * COUT + c0) * HP + trow) * WP;
    float* pmax1 = g_pmax + (((size_t)b * COUT + c1) * HP + trow) * WP;
    float* pmin1 = g_pmin + (((size_t)b * COUT + c1) * HP + trow) * WP;

#pragma unroll
    for (int nt = 0; nt < 2; nt++) {
#pragma unroll
        for (int e = 0; e < 2; e++) {
            const int tcol = chunk * 32 + warp_n * 16 + nt * 8 + 2 * lq + e;
            if (tcol < WP) {
                float v00 = Y[nt][0][0][e] + bv0, v01 = Y[nt][0][1][e] + bv0;
                float v10 = Y[nt][1][0][e] + bv0, v11 = Y[nt][1][1][e] + bv0;
                float w00 = Y[nt][0][0][e+2] + bv1, w01 = Y[nt][0][1][e+2] + bv1;
                float w10 = Y[nt][1][0][e+2] + bv1, w11 = Y[nt][1][1][e+2] + bv1;

                sacc += (v00 + v01 + v10 + v11) + (w00 + w01 + w10 + w11);
                qacc += v00*v00 + v01*v01 + v10*v10 + v11*v11
                      + w00*w00 + w01*w01 + w10*w10 + w11*w11;

                pmax0[tcol] = fmaxf(fmaxf(v00, v01), fmaxf(v10, v11));
                pmin0[tcol] = fminf(fminf(v00, v01), fminf(v10, v11));
                pmax1[tcol] = fmaxf(fmaxf(w00, w01), fmaxf(w10, w11));
                pmin1[tcol] = fminf(fminf(w00, w01), fminf(w10, w11));
            }
        }
    }
#pragma unroll
    for (int off = 16; off > 0; off >>= 1) {
        sacc += __shfl_xor_sync(0xFFFFFFFF, sacc, off);
        qacc += __shfl_xor_sync(0xFFFFFFFF, qacc, off);
    }
    if (lane == 0) {
        atomicAdd(&g_sum[b * NGRP + warp_m], sacc);
        atomicAdd(&g_sumsq[b * NGRP + warp_m], qacc);
    }
}

// ---------------- kernel 2: normalize + clamp (stats inline) -----------------
__global__ __launch_bounds__(256)
void final_kernel(const float* __restrict__ scale,
                  const float* __restrict__ gamma,
                  const float* __restrict__ beta,
                  float* __restrict__ out)
{
    const int t = blockIdx.x;              // b*COUT + c
    const int c = t & (COUT - 1);
    const int b = t >> 7;
    const int g = c >> 4;

    const float n = (float)((COUT / NGRP) * HO * WO);
    const float mean = g_sum[b * NGRP + g] / n;
    const float var  = g_sumsq[b * NGRP + g] / n - mean * mean;
    const float rstd = rsqrtf(var + EPS);
    const float a  = rstd * gamma[c] * scale[c];
    const float bb = (beta[c] - mean * rstd * gamma[c]) * scale[c];

    const size_t base = (size_t)t * (HP * WP);
    const float* src = (a >= 0.f) ? (g_pmax + base) : (g_pmin + base);
    float* dst = out + base;

    float v[16];
#pragma unroll
    for (int u = 0; u < 16; u++) {
        int p = threadIdx.x + u * 256;
        v[u] = (p < HP * WP) ? __ldcs(&src[p]) : 0.f;
    }
#pragma unroll
    for (int u = 0; u < 16; u++) {
        int p = threadIdx.x + u * 256;
        if (p < HP * WP) {
            float m = a * v[u] + bb;
            dst[p] = fminf(fmaxf(m, 0.0f), 1.0f);
        }
    }
}

// ---------------- host launcher ----------------
extern "C" void kernel_launch(void* const* d_in, const int* in_sizes, int n_in,
                              void* d_out, int out_size)
{
    const float* x     = (const float*)d_in[0];
    const float* W     = (const float*)d_in[1];
    const float* bias  = (const float*)d_in[2];
    const float* scale = (const float*)d_in[3];
    const float* gamma = (const float*)d_in[4];
    const float* beta  = (const float*)d_in[5];
    float* out = (float*)d_out;

    static int smem_set = 0;
    const int smem_bytes = SMEM_WORDS * 4;    // 212992
    if (!smem_set) {
        cudaFuncSetAttribute(conv_wino_kernel,
                             cudaFuncAttributeMaxDynamicSharedMemorySize, smem_bytes);
        smem_set = 1;
    }

    pack_kernel<<<256, 256>>>(W);

    dim3 cgrid(2 * HP, BATCH);       // 126 x 32
    conv_wino_kernel<<<cgrid, 512, smem_bytes>>>(x, bias);

    final_kernel<<<BATCH * COUT, 256>>>(scale, gamma, beta, out);
}

// round 16
// speedup vs baseline: 1.3596x; 1.3596x over previous
#include <cuda_runtime.h>
#include <cuda_fp16.h>
#include <cstdint>

// ---------------- problem shape ----------------
#define BATCH 32
#define CIN   64
#define HIN   128
#define WIN   128
#define COUT  128
#define HO    126
#define WO    126
#define NGRP  8
#define HP    63
#define WP    63
#define EPS   1e-5f

#define RSTRIDE 276                    // raw f32 words per ci: 4 rows * 68 + 4 pad
#define RAWW (16 * RSTRIDE)            // 4416 words = 17.6 KB
#define VTS  40                        // tile stride in V (32 + 8; lq*40+lr covers 32 banks)
#define VWORDS (64 * 8 * VTS)          // 20480 words = 80 KB
#define SMEM_WORDS (VWORDS + RAWW)     // 24896 words = 99584 B  (2 CTAs/SM)

// ---------------- scratch (static device globals) ----------------
__device__ float    g_pmax[(size_t)BATCH * COUT * HP * WP];
__device__ float    g_pmin[(size_t)BATCH * COUT * HP * WP];
__device__ uint32_t g_wU[64 * 8 * 32 * 4];   // U fragments; per-(xi,cg,mt) uint4 rows
__device__ float    g_sum[BATCH * NGRP];
__device__ float    g_sumsq[BATCH * NGRP];

// non-volatile: allow ptxas to software-pipeline loads across MMAs
static __device__ __forceinline__ void mma_f16(
    float* c, const uint32_t* a, uint32_t b0, uint32_t b1)
{
    asm("mma.sync.aligned.m16n8k16.row.col.f32.f16.f16.f32 "
        "{%0,%1,%2,%3}, {%4,%5,%6,%7}, {%8,%9}, {%0,%1,%2,%3};"
        : "+f"(c[0]), "+f"(c[1]), "+f"(c[2]), "+f"(c[3])
        : "r"(a[0]), "r"(a[1]), "r"(a[2]), "r"(a[3]), "r"(b0), "r"(b1));
}

// U = G w G^T element (Xi, Nu) for one (cout, ci)
static __device__ __forceinline__ float wino_u(
    const float* __restrict__ W, int cout, int ci, int Xi, int Nu)
{
    const float* w = W + (cout * CIN + ci) * 9;
    float t0, t1, t2;
    if (Xi == 0)      { t0 = w[0]; t1 = w[1]; t2 = w[2]; }
    else if (Xi == 3) { t0 = w[6]; t1 = w[7]; t2 = w[8]; }
    else {
        float s = (Xi == 1) ? 1.f : -1.f;
        t0 = 0.5f * (w[0] + s * w[3] + w[6]);
        t1 = 0.5f * (w[1] + s * w[4] + w[7]);
        t2 = 0.5f * (w[2] + s * w[5] + w[8]);
    }
    if (Nu == 0) return t0;
    if (Nu == 3) return t2;
    float s = (Nu == 1) ? 1.f : -1.f;
    return 0.5f * (t0 + s * t1 + t2);
}

// ---------------- kernel 0: pack U into m16n8k16 fragment layout -------------
// g_wU[((k*8 + mt)*32 + lane)*4 + j], k = xi_nu*4 + cg  (64 total)
__global__ __launch_bounds__(256)
void pack_kernel(const float* __restrict__ W)
{
    int idx = blockIdx.x * 256 + threadIdx.x;      // 65536 total
    if (idx < BATCH * NGRP) { g_sum[idx] = 0.f; g_sumsq[idx] = 0.f; }
    if (idx >= 64 * 8 * 32 * 4) return;
    int j      = idx & 3;
    int lane   = (idx >> 2) & 31;
    int mt     = (idx >> 7) & 7;
    int kchunk = idx >> 10;                        // 0..63
    int xi_nu = kchunk >> 2;
    int cg    = kchunk & 3;
    int Xi = xi_nu >> 2, Nu = xi_nu & 3;
    int lr = lane >> 2, lq = lane & 3;
    int r  = lr + (j & 1) * 8;
    int kb = 2 * lq + ((j >> 1) & 1) * 8;
    int cout = mt * 16 + r;
    int ci   = cg * 16 + kb;
    float u0 = wino_u(W, cout, ci,     Xi, Nu);
    float u1 = wino_u(W, cout, ci + 1, Xi, Nu);
    __half2 h = __floats2half2_rn(u0, u1);         // low = ci even
    g_wU[idx] = *reinterpret_cast<uint32_t*>(&h);
}

// ---------------- kernel 1: Winograd F(2x2,3x3) conv + fused pool ------------
// Grid (126, 32): trow = bx>>1, chunk = bx&1. CTA: 256 thr, 128 couts x 32 tiles.
// 8 warps = 8M x 1N; warp = 16 couts x 32 tiles (nt=0..3). wid == GN group.
// Phase 2 is BARRIER-FREE: V read-only in smem, A prefetched from L2 via LDG.
__global__ __launch_bounds__(256, 2)
void conv_wino_kernel(const float* __restrict__ x,
                      const float* __restrict__ bias)
{
    extern __shared__ uint32_t smw[];
    uint32_t* Vs  = smw;                                      // V tiles (f16x2)
    float*    raw = reinterpret_cast<float*>(smw + VWORDS);   // phase-1 staging

    const int tid  = threadIdx.x;
    const int wid  = tid >> 5;              // 0..7 = m-tile = GN group
    const int lane = tid & 31;
    const int bx = blockIdx.x;
    const int trow  = bx >> 1;              // pooled row 0..62
    const int chunk = bx & 1;
    const int b  = blockIdx.y;
    const int ho0 = trow * 2;
    const int chb = chunk * 64;

    const int lq = lane & 3;
    const int lr = lane >> 2;

    // zero raw pad cols 64..67 (feeds masked/boundary tiles)
    if (tid < 64) {
        int ci = tid >> 2, row = tid & 3;
        *reinterpret_cast<float4*>(raw + ci * RSTRIDE + row * 68 + 64) =
            make_float4(0.f, 0.f, 0.f, 0.f);
    }

    // ======== phase 1: stage x + input transform -> V (f16), per 16-ci chunk ==
    for (int cg = 0; cg < 4; cg++) {
        __syncthreads();
        // stage raw f32: 16 ci x 4 rows x 17 quads = 1088 tasks
#pragma unroll
        for (int t = 0; t < 5; t++) {
            int task = tid + 256 * t;
            if (task < 1088) {
                int ci  = task / 68;
                int rem = task - ci * 68;
                int row = rem / 17;
                int q   = rem - row * 17;
                int col = chb + q * 4;
                if (col <= 124) {
                    float4 v = *reinterpret_cast<const float4*>(
                        x + (((size_t)b * CIN + cg * 16 + ci) * HIN + (ho0 + row)) * WIN + col);
                    *reinterpret_cast<float4*>(raw + ci * RSTRIDE + row * 68 + q * 4) = v;
                }
            }
        }
        __syncthreads();

        // transform: thread = (pair p, tile tt); V = B^T d B for 2 ci
        {
            int p  = tid >> 5;
            int tt = tid & 31;
            float V2[2][16];
#pragma unroll
            for (int s = 0; s < 2; s++) {
                const float* rw = raw + (2 * p + s) * RSTRIDE + 2 * tt;
                float d[4][4];
#pragma unroll
                for (int r = 0; r < 4; r++) {
                    float2 p0 = *reinterpret_cast<const float2*>(rw + r * 68);
                    float2 p1 = *reinterpret_cast<const float2*>(rw + r * 68 + 2);
                    d[r][0] = p0.x; d[r][1] = p0.y; d[r][2] = p1.x; d[r][3] = p1.y;
                }
                float tm[4][4];
#pragma unroll
                for (int jj = 0; jj < 4; jj++) {
                    tm[0][jj] = d[0][jj] - d[2][jj];
                    tm[1][jj] = d[1][jj] + d[2][jj];
                    tm[2][jj] = d[2][jj] - d[1][jj];
                    tm[3][jj] = d[1][jj] - d[3][jj];
                }
#pragma unroll
                for (int ii = 0; ii < 4; ii++) {
                    V2[s][ii * 4 + 0] = tm[ii][0] - tm[ii][2];
                    V2[s][ii * 4 + 1] = tm[ii][1] + tm[ii][2];
                    V2[s][ii * 4 + 2] = tm[ii][2] - tm[ii][1];
                    V2[s][ii * 4 + 3] = tm[ii][1] - tm[ii][3];
                }
            }
#pragma unroll
            for (int xi = 0; xi < 16; xi++) {
                __half2 h = __floats2half2_rn(V2[0][xi], V2[1][xi]);
                Vs[((cg * 16 + xi) * 8 + p) * VTS + tt] =
                    *reinterpret_cast<uint32_t*>(&h);
            }
        }
    }
    __syncthreads();      // V complete; NO MORE BARRIERS after this point

    // ======== phase 2: 64 flattened (xi,cg) steps; A prefetched via LDG ======
    const uint4* gU = reinterpret_cast<const uint4*>(g_wU);

    float Y[4][2][2][4];      // [nt][r][c][frag]
#pragma unroll
    for (int n = 0; n < 4; n++)
#pragma unroll
        for (int r = 0; r < 2; r++)
#pragma unroll
            for (int c = 0; c < 2; c++)
#pragma unroll
                for (int e = 0; e < 4; e++) Y[n][r][c][e] = 0.f;

    float M[4][4];            // [nt][frag], persists across cg within one xi
    uint4 fa = __ldg(&gU[(0 * 8 + wid) * 32 + lane]);

#pragma unroll
    for (int k = 0; k < 64; k++) {
        const int xi = k >> 2, cg = k & 3;

        if (cg == 0) {
#pragma unroll
            for (int n = 0; n < 4; n++)
#pragma unroll
                for (int e = 0; e < 4; e++) M[n][e] = 0.f;
        }

        uint4 fn;
        if (k < 63) fn = __ldg(&gU[((k + 1) * 8 + wid) * 32 + lane]);

        uint32_t a[4] = { fa.x, fa.y, fa.z, fa.w };
        const uint32_t* vb0 = Vs + ((cg * 16 + xi) * 8 + lq)     * VTS + lr;
        const uint32_t* vb1 = Vs + ((cg * 16 + xi) * 8 + lq + 4) * VTS + lr;
#pragma unroll
        for (int nt = 0; nt < 4; nt++) {
            uint32_t b0 = vb0[nt * 8];
            uint32_t b1 = vb1[nt * 8];
            mma_f16(M[nt], a, b0, b1);
        }
        fa = fn;

        if (cg == 3) {
            const int Xi = xi >> 2, Nu = xi & 3;
            const int cy[2] = { (Xi < 3) ? 1 : 0,
                                (Xi == 1) ? 1 : ((Xi >= 2) ? -1 : 0) };
            const int cx[2] = { (Nu < 3) ? 1 : 0,
                                (Nu == 1) ? 1 : ((Nu >= 2) ? -1 : 0) };
#pragma unroll
            for (int r = 0; r < 2; r++)
#pragma unroll
                for (int c = 0; c < 2; c++) {
                    const int coef = cy[r] * cx[c];
                    if (coef == 1) {
#pragma unroll
                        for (int n = 0; n < 4; n++)
#pragma unroll
                            for (int e = 0; e < 4; e++) Y[n][r][c][e] += M[n][e];
                    } else if (coef == -1) {
#pragma unroll
                        for (int n = 0; n < 4; n++)
#pragma unroll
                            for (int e = 0; e < 4; e++) Y[n][r][c][e] -= M[n][e];
                    }
                }
        }
    }

    // ======== epilogue: bias, GN partials, fused 2x2 max/min, store ========
    float sacc = 0.f, qacc = 0.f;

    const int c0 = wid * 16 + lr;
    const int c1 = c0 + 8;
    const float bv0 = bias[c0];
    const float bv1 = bias[c1];
    float* pmax0 = g_pmax + (((size_t)b * COUT + c0) * HP + trow) * WP;
    float* pmin0 = g_pmin + (((size_t)b * COUT + c0) * HP + trow) * WP;
    float* pmax1 = g_pmax + (((size_t)b * COUT + c1) * HP + trow) * WP;
    float* pmin1 = g_pmin + (((size_t)b * COUT + c1) * HP + trow) * WP;

#pragma unroll
    for (int nt = 0; nt < 4; nt++) {
#pragma unroll
        for (int e = 0; e < 2; e++) {
            const int tcol = chunk * 32 + nt * 8 + 2 * lq + e;
            if (tcol < WP) {
                float v00 = Y[nt][0][0][e] + bv0, v01 = Y[nt][0][1][e] + bv0;
                float v10 = Y[nt][1][0][e] + bv0, v11 = Y[nt][1][1][e] + bv0;
                float w00 = Y[nt][0][0][e+2] + bv1, w01 = Y[nt][0][1][e+2] + bv1;
                float w10 = Y[nt][1][0][e+2] + bv1, w11 = Y[nt][1][1][e+2] + bv1;

                sacc += (v00 + v01 + v10 + v11) + (w00 + w01 + w10 + w11);
                qacc += v00*v00 + v01*v01 + v10*v10 + v11*v11
                      + w00*w00 + w01*w01 + w10*w10 + w11*w11;

                pmax0[tcol] = fmaxf(fmaxf(v00, v01), fmaxf(v10, v11));
                pmin0[tcol] = fminf(fminf(v00, v01), fminf(v10, v11));
                pmax1[tcol] = fmaxf(fmaxf(w00, w01), fmaxf(w10, w11));
                pmin1[tcol] = fminf(fminf(w00, w01), fminf(w10, w11));
            }
        }
    }
#pragma unroll
    for (int off = 16; off > 0; off >>= 1) {
        sacc += __shfl_xor_sync(0xFFFFFFFF, sacc, off);
        qacc += __shfl_xor_sync(0xFFFFFFFF, qacc, off);
    }
    if (lane == 0) {
        atomicAdd(&g_sum[b * NGRP + wid], sacc);
        atomicAdd(&g_sumsq[b * NGRP + wid], qacc);
    }
}

// ---------------- kernel 2: normalize + clamp (stats inline) -----------------
__global__ __launch_bounds__(256)
void final_kernel(const float* __restrict__ scale,
                  const float* __restrict__ gamma,
                  const float* __restrict__ beta,
                  float* __restrict__ out)
{
    const int t = blockIdx.x;              // b*COUT + c
    const int c = t & (COUT - 1);
    const int b = t >> 7;
    const int g = c >> 4;

    const float n = (float)((COUT / NGRP) * HO * WO);
    const float mean = g_sum[b * NGRP + g] / n;
    const float var  = g_sumsq[b * NGRP + g] / n - mean * mean;
    const float rstd = rsqrtf(var + EPS);
    const float a  = rstd * gamma[c] * scale[c];
    const float bb = (beta[c] - mean * rstd * gamma[c]) * scale[c];

    const size_t base = (size_t)t * (HP * WP);
    const float* src = (a >= 0.f) ? (g_pmax + base) : (g_pmin + base);
    float* dst = out + base;

    float v[16];
#pragma unroll
    for (int u = 0; u < 16; u++) {
        int p = threadIdx.x + u * 256;
        v[u] = (p < HP * WP) ? __ldcs(&src[p]) : 0.f;
    }
#pragma unroll
    for (int u = 0; u < 16; u++) {
        int p = threadIdx.x + u * 256;
        if (p < HP * WP) {
            float m = a * v[u] + bb;
            dst[p] = fminf(fmaxf(m, 0.0f), 1.0f);
        }
    }
}

// ---------------- host launcher ----------------
extern "C" void kernel_launch(void* const* d_in, const int* in_sizes, int n_in,
                              void* d_out, int out_size)
{
    const float* x     = (const float*)d_in[0];
    const float* W     = (const float*)d_in[1];
    const float* bias  = (const float*)d_in[2];
    const float* scale = (const float*)d_in[3];
    const float* gamma = (const float*)d_in[4];
    const float* beta  = (const float*)d_in[5];
    float* out = (float*)d_out;

    static int smem_set = 0;
    const int smem_bytes = SMEM_WORDS * 4;    // 99584
    if (!smem_set) {
        cudaFuncSetAttribute(conv_wino_kernel,
                             cudaFuncAttributeMaxDynamicSharedMemorySize, smem_bytes);
        smem_set = 1;
    }

    pack_kernel<<<256, 256>>>(W);

    dim3 cgrid(2 * HP, BATCH);       // 126 x 32
    conv_wino_kernel<<<cgrid, 256, smem_bytes>>>(x, bias);

    final_kernel<<<BATCH * COUT, 256>>>(scale, gamma, beta, out);
}

// round 17
// speedup vs baseline: 1.3679x; 1.0061x over previous
#include <cuda_runtime.h>
#include <cuda_fp16.h>
#include <cstdint>

// ---------------- problem shape ----------------
#define BATCH 32
#define CIN   64
#define HIN   128
#define WIN   128
#define COUT  128
#define HO    126
#define WO    126
#define NGRP  8
#define HP    63
#define WP    63
#define EPS   1e-5f

#define RSTRIDE 276                    // raw f32 words per ci: 4 rows * 68 + 4 pad
#define RAWW (16 * RSTRIDE)            // 4416 words = 17.6 KB
#define VTS  40                        // tile stride in V (32 + 8; 8lq+lr covers 32 banks)
#define VWORDS (64 * 8 * VTS)          // 20480 words = 80 KB
#define SMEM_WORDS (VWORDS + RAWW)     // 24896 words = 99584 B  (2 CTAs/SM)

// ---------------- scratch (static device globals) ----------------
__device__ float    g_pmax[(size_t)BATCH * COUT * HP * WP];
__device__ float    g_pmin[(size_t)BATCH * COUT * HP * WP];
__device__ uint32_t g_wU[64 * 8 * 32 * 4];   // U fragments; per-(xi,cg,mt) uint4 rows
__device__ float    g_sum[BATCH * NGRP];
__device__ float    g_sumsq[BATCH * NGRP];

// non-volatile: allow ptxas to software-pipeline loads across MMAs
static __device__ __forceinline__ void mma_f16(
    float* c, const uint32_t* a, uint32_t b0, uint32_t b1)
{
    asm("mma.sync.aligned.m16n8k16.row.col.f32.f16.f16.f32 "
        "{%0,%1,%2,%3}, {%4,%5,%6,%7}, {%8,%9}, {%0,%1,%2,%3};"
        : "+f"(c[0]), "+f"(c[1]), "+f"(c[2]), "+f"(c[3])
        : "r"(a[0]), "r"(a[1]), "r"(a[2]), "r"(a[3]), "r"(b0), "r"(b1));
}

// U = G w G^T element (Xi, Nu) for one (cout, ci)
static __device__ __forceinline__ float wino_u(
    const float* __restrict__ W, int cout, int ci, int Xi, int Nu)
{
    const float* w = W + (cout * CIN + ci) * 9;
    float t0, t1, t2;
    if (Xi == 0)      { t0 = w[0]; t1 = w[1]; t2 = w[2]; }
    else if (Xi == 3) { t0 = w[6]; t1 = w[7]; t2 = w[8]; }
    else {
        float s = (Xi == 1) ? 1.f : -1.f;
        t0 = 0.5f * (w[0] + s * w[3] + w[6]);
        t1 = 0.5f * (w[1] + s * w[4] + w[7]);
        t2 = 0.5f * (w[2] + s * w[5] + w[8]);
    }
    if (Nu == 0) return t0;
    if (Nu == 3) return t2;
    float s = (Nu == 1) ? 1.f : -1.f;
    return 0.5f * (t0 + s * t1 + t2);
}

// ---------------- kernel 0: pack U into m16n8k16 fragment layout -------------
// g_wU[((k*8 + mt)*32 + lane)*4 + j], k = xi_nu*4 + cg  (64 total)
__global__ __launch_bounds__(256)
void pack_kernel(const float* __restrict__ W)
{
    int idx = blockIdx.x * 256 + threadIdx.x;      // 65536 total
    if (idx < BATCH * NGRP) { g_sum[idx] = 0.f; g_sumsq[idx] = 0.f; }
    if (idx >= 64 * 8 * 32 * 4) return;
    int j      = idx & 3;
    int lane   = (idx >> 2) & 31;
    int mt     = (idx >> 7) & 7;
    int kchunk = idx >> 10;                        // 0..63
    int xi_nu = kchunk >> 2;
    int cg    = kchunk & 3;
    int Xi = xi_nu >> 2, Nu = xi_nu & 3;
    int lr = lane >> 2, lq = lane & 3;
    int r  = lr + (j & 1) * 8;
    int kb = 2 * lq + ((j >> 1) & 1) * 8;
    int cout = mt * 16 + r;
    int ci   = cg * 16 + kb;
    float u0 = wino_u(W, cout, ci,     Xi, Nu);
    float u1 = wino_u(W, cout, ci + 1, Xi, Nu);
    __half2 h = __floats2half2_rn(u0, u1);         // low = ci even
    g_wU[idx] = *reinterpret_cast<uint32_t*>(&h);
}

// ---------------- kernel 1: Winograd F(2x2,3x3) conv + fused pool ------------
// Grid (126, 32): trow = bx>>1, chunk = bx&1. CTA: 256 thr, 128 couts x 32 tiles.
// 8 warps = 8M x 1N; warp = 16 couts x 32 tiles (nt=0..3). wid == GN group.
// Phase 2 barrier-free; A fragments LDG-prefetched with ring depth 4 (MLP=4).
__global__ __launch_bounds__(256, 2)
void conv_wino_kernel(const float* __restrict__ x,
                      const float* __restrict__ bias)
{
    extern __shared__ uint32_t smw[];
    uint32_t* Vs  = smw;                                      // V tiles (f16x2)
    float*    raw = reinterpret_cast<float*>(smw + VWORDS);   // phase-1 staging

    const int tid  = threadIdx.x;
    const int wid  = tid >> 5;              // 0..7 = m-tile = GN group
    const int lane = tid & 31;
    const int bx = blockIdx.x;
    const int trow  = bx >> 1;              // pooled row 0..62
    const int chunk = bx & 1;
    const int b  = blockIdx.y;
    const int ho0 = trow * 2;
    const int chb = chunk * 64;

    const int lq = lane & 3;
    const int lr = lane >> 2;

    // zero raw pad cols 64..67 (feeds masked/boundary tiles)
    if (tid < 64) {
        int ci = tid >> 2, row = tid & 3;
        *reinterpret_cast<float4*>(raw + ci * RSTRIDE + row * 68 + 64) =
            make_float4(0.f, 0.f, 0.f, 0.f);
    }

    // ======== phase 1: stage x + input transform -> V (f16), per 16-ci chunk ==
    for (int cg = 0; cg < 4; cg++) {
        __syncthreads();
#pragma unroll
        for (int t = 0; t < 5; t++) {
            int task = tid + 256 * t;
            if (task < 1088) {
                int ci  = task / 68;
                int rem = task - ci * 68;
                int row = rem / 17;
                int q   = rem - row * 17;
                int col = chb + q * 4;
                if (col <= 124) {
                    float4 v = *reinterpret_cast<const float4*>(
                        x + (((size_t)b * CIN + cg * 16 + ci) * HIN + (ho0 + row)) * WIN + col);
                    *reinterpret_cast<float4*>(raw + ci * RSTRIDE + row * 68 + q * 4) = v;
                }
            }
        }
        __syncthreads();

        // transform: thread = (pair p, tile tt); V = B^T d B for 2 ci
        {
            int p  = tid >> 5;
            int tt = tid & 31;
            float V2[2][16];
#pragma unroll
            for (int s = 0; s < 2; s++) {
                const float* rw = raw + (2 * p + s) * RSTRIDE + 2 * tt;
                float d[4][4];
#pragma unroll
                for (int r = 0; r < 4; r++) {
                    float2 p0 = *reinterpret_cast<const float2*>(rw + r * 68);
                    float2 p1 = *reinterpret_cast<const float2*>(rw + r * 68 + 2);
                    d[r][0] = p0.x; d[r][1] = p0.y; d[r][2] = p1.x; d[r][3] = p1.y;
                }
                float tm[4][4];
#pragma unroll
                for (int jj = 0; jj < 4; jj++) {
                    tm[0][jj] = d[0][jj] - d[2][jj];
                    tm[1][jj] = d[1][jj] + d[2][jj];
                    tm[2][jj] = d[2][jj] - d[1][jj];
                    tm[3][jj] = d[1][jj] - d[3][jj];
                }
#pragma unroll
                for (int ii = 0; ii < 4; ii++) {
                    V2[s][ii * 4 + 0] = tm[ii][0] - tm[ii][2];
                    V2[s][ii * 4 + 1] = tm[ii][1] + tm[ii][2];
                    V2[s][ii * 4 + 2] = tm[ii][2] - tm[ii][1];
                    V2[s][ii * 4 + 3] = tm[ii][1] - tm[ii][3];
                }
            }
#pragma unroll
            for (int xi = 0; xi < 16; xi++) {
                __half2 h = __floats2half2_rn(V2[0][xi], V2[1][xi]);
                Vs[((cg * 16 + xi) * 8 + p) * VTS + tt] =
                    *reinterpret_cast<uint32_t*>(&h);
            }
        }
    }
    __syncthreads();      // V complete; NO MORE BARRIERS after this point

    // ======== phase 2: 64 (xi,cg) steps; A LDG ring buffer depth 4 ========
    const uint4* gU = reinterpret_cast<const uint4*>(g_wU) + wid * 32 + lane;

    float Y[4][2][2][4];      // [nt][r][c][frag]
#pragma unroll
    for (int n = 0; n < 4; n++)
#pragma unroll
        for (int r = 0; r < 2; r++)
#pragma unroll
            for (int c = 0; c < 2; c++)
#pragma unroll
                for (int e = 0; e < 4; e++) Y[n][r][c][e] = 0.f;

    float M[4][4];            // [nt][frag], persists across cg within one xi
    uint4 fq[4];
#pragma unroll
    for (int i = 0; i < 4; i++)
        fq[i] = __ldg(gU + i * 256);       // step i (k*8*32 stride = 256 uint4)

#pragma unroll
    for (int k = 0; k < 64; k++) {
        const int xi = k >> 2, cg = k & 3;

        if (cg == 0) {
#pragma unroll
            for (int n = 0; n < 4; n++)
#pragma unroll
                for (int e = 0; e < 4; e++) M[n][e] = 0.f;
        }

        uint4 fa = fq[k & 3];
        if (k + 4 < 64) fq[k & 3] = __ldg(gU + (k + 4) * 256);

        uint32_t a[4] = { fa.x, fa.y, fa.z, fa.w };
        const uint32_t* vb0 = Vs + ((cg * 16 + xi) * 8 + lq)     * VTS + lr;
        const uint32_t* vb1 = Vs + ((cg * 16 + xi) * 8 + lq + 4) * VTS + lr;
#pragma unroll
        for (int nt = 0; nt < 4; nt++) {
            uint32_t b0 = vb0[nt * 8];
            uint32_t b1 = vb1[nt * 8];
            mma_f16(M[nt], a, b0, b1);
        }

        if (cg == 3) {
            const int Xi = xi >> 2, Nu = xi & 3;
            const int cy[2] = { (Xi < 3) ? 1 : 0,
                                (Xi == 1) ? 1 : ((Xi >= 2) ? -1 : 0) };
            const int cx[2] = { (Nu < 3) ? 1 : 0,
                                (Nu == 1) ? 1 : ((Nu >= 2) ? -1 : 0) };
#pragma unroll
            for (int r = 0; r < 2; r++)
#pragma unroll
                for (int c = 0; c < 2; c++) {
                    const int coef = cy[r] * cx[c];
                    if (coef == 1) {
#pragma unroll
                        for (int n = 0; n < 4; n++)
#pragma unroll
                            for (int e = 0; e < 4; e++) Y[n][r][c][e] += M[n][e];
                    } else if (coef == -1) {
#pragma unroll
                        for (int n = 0; n < 4; n++)
#pragma unroll
                            for (int e = 0; e < 4; e++) Y[n][r][c][e] -= M[n][e];
                    }
                }
        }
    }

    // ======== epilogue: bias, GN partials, fused 2x2 max/min, store ========
    float sacc = 0.f, qacc = 0.f;

    const int c0 = wid * 16 + lr;
    const int c1 = c0 + 8;
    const float bv0 = bias[c0];
    const float bv1 = bias[c1];
    float* pmax0 = g_pmax + (((size_t)b * COUT + c0) * HP + trow) * WP;
    float* pmin0 = g_pmin + (((size_t)b * COUT + c0) * HP + trow) * WP;
    float* pmax1 = g_pmax + (((size_t)b * COUT + c1) * HP + trow) * WP;
    float* pmin1 = g_pmin + (((size_t)b * COUT + c1) * HP + trow) * WP;

#pragma unroll
    for (int nt = 0; nt < 4; nt++) {
#pragma unroll
        for (int e = 0; e < 2; e++) {
            const int tcol = chunk * 32 + nt * 8 + 2 * lq + e;
            if (tcol < WP) {
                float v00 = Y[nt][0][0][e] + bv0, v01 = Y[nt][0][1][e] + bv0;
                float v10 = Y[nt][1][0][e] + bv0, v11 = Y[nt][1][1][e] + bv0;
                float w00 = Y[nt][0][0][e+2] + bv1, w01 = Y[nt][0][1][e+2] + bv1;
                float w10 = Y[nt][1][0][e+2] + bv1, w11 = Y[nt][1][1][e+2] + bv1;

                sacc += (v00 + v01 + v10 + v11) + (w00 + w01 + w10 + w11);
                qacc += v00*v00 + v01*v01 + v10*v10 + v11*v11
                      + w00*w00 + w01*w01 + w10*w10 + w11*w11;

                pmax0[tcol] = fmaxf(fmaxf(v00, v01), fmaxf(v10, v11));
                pmin0[tcol] = fminf(fminf(v00, v01), fminf(v10, v11));
                pmax1[tcol] = fmaxf(fmaxf(w00, w01), fmaxf(w10, w11));
                pmin1[tcol] = fminf(fminf(w00, w01), fminf(w10, w11));
            }
        }
    }
#pragma unroll
    for (int off = 16; off > 0; off >>= 1) {
        sacc += __shfl_xor_sync(0xFFFFFFFF, sacc, off);
        qacc += __shfl_xor_sync(0xFFFFFFFF, qacc, off);
    }
    if (lane == 0) {
        atomicAdd(&g_sum[b * NGRP + wid], sacc);
        atomicAdd(&g_sumsq[b * NGRP + wid], qacc);
    }
}

// ---------------- kernel 2: normalize + clamp (stats inline) -----------------
__global__ __launch_bounds__(256)
void final_kernel(const float* __restrict__ scale,
                  const float* __restrict__ gamma,
                  const float* __restrict__ beta,
                  float* __restrict__ out)
{
    const int t = blockIdx.x;              // b*COUT + c
    const int c = t & (COUT - 1);
    const int b = t >> 7;
    const int g = c >> 4;

    const float n = (float)((COUT / NGRP) * HO * WO);
    const float mean = g_sum[b * NGRP + g] / n;
    const float var  = g_sumsq[b * NGRP + g] / n - mean * mean;
    const float rstd = rsqrtf(var + EPS);
    const float a  = rstd * gamma[c] * scale[c];
    const float bb = (beta[c] - mean * rstd * gamma[c]) * scale[c];

    const size_t base = (size_t)t * (HP * WP);
    const float* src = (a >= 0.f) ? (g_pmax + base) : (g_pmin + base);
    float* dst = out + base;

    float v[16];
#pragma unroll
    for (int u = 0; u < 16; u++) {
        int p = threadIdx.x + u * 256;
        v[u] = (p < HP * WP) ? __ldcs(&src[p]) : 0.f;
    }
#pragma unroll
    for (int u = 0; u < 16; u++) {
        int p = threadIdx.x + u * 256;
        if (p < HP * WP) {
            float m = a * v[u] + bb;
            dst[p] = fminf(fmaxf(m, 0.0f), 1.0f);
        }
    }
}

// ---------------- host launcher ----------------
extern "C" void kernel_launch(void* const* d_in, const int* in_sizes, int n_in,
                              void* d_out, int out_size)
{
    const float* x     = (const float*)d_in[0];
    const float* W     = (const float*)d_in[1];
    const float* bias  = (const float*)d_in[2];
    const float* scale = (const float*)d_in[3];
    const float* gamma = (const float*)d_in[4];
    const float* beta  = (const float*)d_in[5];
    float* out = (float*)d_out;

    static int smem_set = 0;
    const int smem_bytes = SMEM_WORDS * 4;    // 99584
    if (!smem_set) {
        cudaFuncSetAttribute(conv_wino_kernel,
                             cudaFuncAttributeMaxDynamicSharedMemorySize, smem_bytes);
        smem_set = 1;
    }

    pack_kernel<<<256, 256>>>(W);

    dim3 cgrid(2 * HP, BATCH);       // 126 x 32
    conv_wino_kernel<<<cgrid, 256, smem_bytes>>>(x, bias);

    final_kernel<<<BATCH * COUT, 256>>>(scale, gamma, beta, out);
}